// round 12
// baseline (speedup 1.0000x reference)
#include <cuda_runtime.h>
#include <cuda_fp16.h>
#include <cstdint>
#include <cstddef>

#define NB     16
#define NN     256
#define NT     4
#define HD     128
#define NL     2
#define CELLS  (NB*NN)
#define LOFF   (CELLS*HD)
#define MAXST  15
#define OUTV   1000
#define NCTA   128
#define ZSTR   132

typedef __half f16;

// ---------------- device scratch ----------------
__device__ float g_c_st [NL*CELLS*HD];
__device__ float g_h_st [NL*CELLS*HD];
__device__ float g_pubC [2][NL*CELLS*HD];
__device__ float g_pubH [2][NL*CELLS*HD];
__device__ f16   g_embf_h[CELLS*NT*HD];
__device__ f16   g_embf_l[CELLS*NT*HD];
__device__ float g_xw   [CELLS*NT*512];    // layout: [cell*4+t][d*4+gate]
__device__ f16   g_w0xf [512*128];         // Wi(l0)^T, block permutation, fp16
__device__ f16   g_w0t  [512*128];         // Wh0^T, interleaved permutation, fp16
__device__ f16   g_w1t  [512*256];         // [Wi1;Wh1]^T, interleaved permutation, fp16
__device__ float g_wtb[2][CELLS], g_wfb[2][CELLS];
__device__ int   g_csr_off[NB*NN];
__device__ int   g_csr_ent[NB*NN*2];
__device__ unsigned g_bctr[NB];
__device__ unsigned g_bgen[NB];

__device__ __forceinline__ float tanhap(float x){
    float r; asm("tanh.approx.f32 %0, %1;" : "=f"(r) : "f"(x)); return r;
}
__device__ __forceinline__ float sigf(float x){ return fmaf(tanhap(0.5f*x), 0.5f, 0.5f); }

__device__ __forceinline__ uint32_t smem_u32(const void* p){
    uint32_t a; asm("{ .reg .u64 t; cvta.to.shared.u64 t, %1; cvt.u32.u64 %0, t; }":"=r"(a):"l"(p)); return a;
}
#define CPA16(d,s) asm volatile("cp.async.cg.shared.global [%0], [%1], 16;"::"r"(d),"l"((unsigned long long)__cvta_generic_to_global((const void*)(s))):"memory")
#define CP_COMMIT() asm volatile("cp.async.commit_group;":::"memory")

__device__ __forceinline__ void ldmx4(uint32_t* r, uint32_t a){
    asm volatile("ldmatrix.sync.aligned.m8n8.x4.shared.b16 {%0,%1,%2,%3}, [%4];"
        : "=r"(r[0]),"=r"(r[1]),"=r"(r[2]),"=r"(r[3]) : "r"(a));
}
__device__ __forceinline__ void ldmx2(uint32_t* r, uint32_t a){
    asm volatile("ldmatrix.sync.aligned.m8n8.x2.shared.b16 {%0,%1}, [%2];"
        : "=r"(r[0]),"=r"(r[1]) : "r"(a));
}
__device__ __forceinline__ void mmaf16(float* d, const uint32_t* a, const uint32_t* b){
    asm volatile("mma.sync.aligned.m16n8k16.row.col.f32.f16.f16.f32 "
        "{%0,%1,%2,%3}, {%4,%5,%6,%7}, {%8,%9}, {%0,%1,%2,%3};"
        : "+f"(d[0]),"+f"(d[1]),"+f"(d[2]),"+f"(d[3])
        : "r"(a[0]),"r"(a[1]),"r"(a[2]),"r"(a[3]),"r"(b[0]),"r"(b[1]));
}

__device__ __forceinline__ void batchsync(int b, unsigned &cnt){
    __syncthreads();
    if (threadIdx.x == 0){
        __threadfence();
        unsigned t = ++cnt;
        if (atomicAdd(&g_bctr[b], 1u) == 7u){
            atomicExch(&g_bctr[b], 0u);
            __threadfence();
            *(volatile unsigned*)&g_bgen[b] = t;
        } else {
            while (*(volatile unsigned*)&g_bgen[b] < t) __nanosleep(32);
        }
        __threadfence();
    }
    __syncthreads();
}

// smem layout (bytes, from 1KB-aligned base)
#define SW_OFF   0u          // W double buffer: 2 x 65536
#define H0H_OFF  131072u
#define H1H_OFF  139264u
#define C0_OFF   147456u
#define C1_OFF   163840u
#define SNAP_OFF 180224u
#define SWT_OFF  182272u
#define SWF_OFF  183296u
#define IP_OFF   184320u
#define WBS_OFF  184448u
#define BLS_OFF  188544u
#define SM_NEED  (192640u + 1024u)

__device__ __forceinline__ float hrd1(const char* hh, int row, int d){
    uint32_t off = (uint32_t)(row*256) + ((uint32_t)((d>>3) ^ (row&7))<<4) + (uint32_t)((d&7)*2);
    return __half2float(*(const f16*)(hh+off));
}
__device__ __forceinline__ void hwr1(char* hh, int row, int d, float v){
    uint32_t off = (uint32_t)(row*256) + ((uint32_t)((d>>3) ^ (row&7))<<4) + (uint32_t)((d&7)*2);
    *(f16*)(hh+off) = __float2half(v);
}

// ==================== persistent kernel ====================
__global__ __launch_bounds__(512,1) void persist(
    const int* __restrict__ exi, const int* __restrict__ steps,
    const float* __restrict__ bl, const float* __restrict__ Wb,
    const float* __restrict__ bb)
{
    extern __shared__ char dsm[];
    const uint32_t S0 = smem_u32(dsm);
    const uint32_t S  = (S0 + 1023u) & ~1023u;
    char* base = dsm + (S - S0);
    char* h0h = base + H0H_OFF;
    char* h1h = base + H1H_OFF;
    float* c0 = (float*)(base + C0_OFF);
    float* c1 = (float*)(base + C1_OFF);
    float* snC0 = (float*)(base + SNAP_OFF);
    float* snC1 = snC0 + 128; float* snH0 = snC0 + 256; float* snH1 = snC0 + 384;
    float* swt = (float*)(base + SWT_OFF);
    float* swf = (float*)(base + SWF_OFF);
    float* ips = (float*)(base + IP_OFF);
    float* wbs = (float*)(base + WBS_OFF);
    float* bls = (float*)(base + BLS_OFF);

    const int tid = threadIdx.x, lane = tid & 31, wid = tid >> 5;
    const int bid = blockIdx.x;
    const int b = bid >> 3, cell0 = bid * 32, lb = (bid & 7) * 32;
    const int mw = wid & 1, nw = wid >> 1;
    const int qr = lane >> 2, qc = (lane & 3) * 2;

    int wpar = 0;
    auto pref = [&](const f16* src, int KK, int buf){
        uint32_t dst = S + SW_OFF + (uint32_t)buf*65536u;
        #pragma unroll
        for (int i = 0; i < 8; ++i){
            int idx = tid + i*512;
            int row = idx >> 3, c16 = idx & 7;
            CPA16(dst + (uint32_t)(row*128) + ((uint32_t)(c16 ^ (row&7))<<4),
                  src + (size_t)row*KK + c16*8);
        }
        CP_COMMIT();
    };

    pref(g_w0t, 128, 0);   // kick off continuous W pipeline

    // init state
    for (int i = tid; i < 2048; i += 512){
        ((uint32_t*)h0h)[i] = 0; ((uint32_t*)h1h)[i] = 0;
    }
    for (int i = tid; i < 4096; i += 512){ c0[i] = 0.f; c1[i] = 0.f; }
    if (tid < 32) ips[tid] = (cell0 + tid == b*256) ? 1.0f : 0.0f;
    for (int i = tid; i < 1024; i += 512){ wbs[i] = __ldg(Wb + i); bls[i] = __ldg(bl + i); }
    __syncthreads();

    const int el = __ldg(exi + b);
    const bool owned = (el >> 5) == (bid & 7);
    const int eloc = el & 31;
    const int nsteps = __ldg(steps + b);
    const float bb0 = __ldg(bb), bb1 = __ldg(bb + 1);

    // fused GEMM (M=32,N=512) + LSTM epilogue; continuous W pipeline
    auto gemm = [&](int nslab, const f16* wsrc, int KK,
                    const f16* nextw, int nextKK,
                    const char* aHi0, const char* aHi1,
                    const float* xwp, const float* bias,
                    float* cbuf, char* hOh)
    {
        float acc[8][4];
        #pragma unroll
        for (int n8=0;n8<8;++n8){ acc[n8][0]=0.f; acc[n8][1]=0.f; acc[n8][2]=0.f; acc[n8][3]=0.f; }

        for (int s = 0; s < nslab; ++s){
            asm volatile("cp.async.wait_group 0;":::"memory");
            __syncthreads();
            if (s + 1 < nslab) pref(wsrc + (s+1)*64, KK, wpar^1);
            else               pref(nextw, nextKK, wpar^1);
            uint32_t wb = S + SW_OFF + (uint32_t)wpar*65536u;
            #pragma unroll
            for (int kk = 0; kk < 4; ++kk){
                int kglob = s*64 + kk*16;
                const char* ah; int kr;
                if (kglob < 128){ ah = aHi0; kr = kglob; }
                else            { ah = aHi1; kr = kglob - 128; }
                int row = mw*16 + (lane & 15);
                uint32_t u = (uint32_t)(((kr >> 3) + (lane >> 4)) ^ (row & 7));
                uint32_t Ah[4];
                ldmx4(Ah, smem_u32(ah) + (uint32_t)(row*256) + (u << 4));
                uint32_t B[4][4];
                #pragma unroll
                for (int p = 0; p < 4; ++p){
                    int r = nw*64 + p*16 + ((lane >> 4) << 3) + (lane & 7);
                    uint32_t kh = (uint32_t)(kk*2 + ((lane >> 3) & 1));
                    ldmx4(B[p], wb + (uint32_t)(r*128) + ((kh ^ (uint32_t)(r & 7)) << 4));
                }
                #pragma unroll
                for (int p = 0; p < 4; ++p){
                    mmaf16(acc[2*p],   Ah, &B[p][0]);
                    mmaf16(acc[2*p+1], Ah, &B[p][2]);
                }
            }
            wpar ^= 1;
        }
        __syncthreads();

        // epilogue: register gate math; xw loaded as one float4 per output
        #pragma unroll
        for (int rh = 0; rh < 2; ++rh){
            int row = mw*16 + qr + rh*8;
            int cell = cell0 + row;
            const float4* xr4 = xwp ? (const float4*)(xwp + (size_t)cell*2048) : nullptr;
            #pragma unroll
            for (int dd = 0; dd < 4; ++dd){
                int dlow = qc + (dd & 1) + (dd >> 1)*8;
                int hb = dd >> 1;
                int e = (dd & 1) + rh*2;
                int d = nw*16 + dlow;
                float vi = acc[hb][e]     + bias[d];
                float vf = acc[2+hb][e]   + bias[128 + d];
                float vg = acc[4+hb][e]   + bias[256 + d];
                float vo = acc[6+hb][e]   + bias[384 + d];
                if (xr4){
                    float4 xv = __ldg(xr4 + d);
                    vi += xv.x; vf += xv.y; vg += xv.z; vo += xv.w;
                }
                float cold = cbuf[row*128 + d];
                float c2 = sigf(vf)*cold + sigf(vi)*tanhap(vg);
                float hv = sigf(vo)*tanhap(c2);
                cbuf[row*128 + d] = c2;
                hwr1(hOh, row, d, hv);
            }
        }
        __syncthreads();
    };

    unsigned scnt = 0;
    for (int s = 0; s < nsteps; ++s){
        int par = s & 1;

        if (owned){
            int a = tid >> 7, d = tid & 127;
            if (a == 0) snC0[d] = c0[eloc*128 + d];
            else if (a == 1) snC1[d] = c1[eloc*128 + d];
            else if (a == 2) snH0[d] = hrd1(h0h, eloc, d);
            else             snH1[d] = hrd1(h1h, eloc, d);
        }
        __syncthreads();

        for (int t = 0; t < NT; ++t){
            gemm(2, g_w0t, 128, g_w1t, 256, h0h, h0h, g_xw + t*512, bls,       c0, h0h);
            gemm(4, g_w1t, 256, g_w0t, 128, h0h, h1h, nullptr,      bls + 512, c1, h1h);
        }

        if (owned){
            int a = tid >> 7, d = tid & 127;
            if (a == 0) c0[eloc*128 + d] = snC0[d];
            else if (a == 1) c1[eloc*128 + d] = snC1[d];
            else if (a == 2) hwr1(h0h, eloc, d, snH0[d]);
            else             hwr1(h1h, eloc, d, snH1[d]);
        }
        __syncthreads();

        // branch + publish
        {
            #pragma unroll
            for (int q = 0; q < 2; ++q){
                int i = wid*2 + q;
                float a0 = 0.f, a1 = 0.f;
                for (int d = lane; d < 128; d += 32){
                    float v0 = c0[i*128 + d];
                    float v1 = hrd1(h0h, i, d);
                    float v2 = c1[i*128 + d];
                    float v3 = hrd1(h1h, i, d);
                    a0 += v0*wbs[2*d]        + v1*wbs[2*(128+d)]
                        + v2*wbs[2*(256+d)]  + v3*wbs[2*(384+d)];
                    a1 += v0*wbs[2*d+1]      + v1*wbs[2*(128+d)+1]
                        + v2*wbs[2*(256+d)+1]+ v3*wbs[2*(384+d)+1];
                }
                #pragma unroll
                for (int o2 = 16; o2; o2 >>= 1){
                    a0 += __shfl_xor_sync(~0u, a0, o2);
                    a1 += __shfl_xor_sync(~0u, a1, o2);
                }
                if (lane == 0){
                    a0 += bb0; a1 += bb1;
                    float m = fmaxf(a0, a1), e0 = __expf(a0-m), e1 = __expf(a1-m);
                    float inv = 1.0f/(e0+e1), w = ips[i];
                    g_wtb[par][cell0 + i] = e0*inv*w;
                    g_wfb[par][cell0 + i] = e1*inv*w;
                }
            }
            for (int v = tid; v < 32*128; v += 512){
                int row = v >> 7, d = v & 127;
                size_t o = (size_t)(cell0 + row)*128 + d;
                g_pubC[par][o]        = c0[row*128 + d];
                g_pubC[par][o + LOFF] = c1[row*128 + d];
                g_pubH[par][o]        = hrd1(h0h, row, d);
                g_pubH[par][o + LOFF] = hrd1(h1h, row, d);
            }
        }
        batchsync(b, scnt);

        // aggregation (CSR)
        for (int i = tid; i < 256; i += 512){
            swt[i] = __ldcg(&g_wtb[par][b*256 + i]);
            swf[i] = __ldcg(&g_wfb[par][b*256 + i]);
        }
        __syncthreads();
        #pragma unroll
        for (int it = 0; it < 8; ++it){
            int i = it*4 + (tid >> 7);
            int d = tid & 127;
            int dstb = lb + i;
            int o0 = g_csr_off[b*NN + dstb];
            int o1 = (dstb == NN-1) ? (b*2*NN + 2*NN) : g_csr_off[b*NN + dstb + 1];
            float a0=0.f, a1=0.f, a2=0.f, a3=0.f, ipn=0.f;
            for (int qq = o0; qq < o1; ++qq){
                int v = g_csr_ent[qq];
                int src = v & 255;
                float w = (v < 0) ? swf[src] : swt[src];
                ipn += w;
                size_t o = (size_t)(b*256 + src)*128 + d;
                a0 += w * __ldcg(&g_pubC[par][o]);
                a1 += w * __ldcg(&g_pubH[par][o]);
                a2 += w * __ldcg(&g_pubC[par][o + LOFF]);
                a3 += w * __ldcg(&g_pubH[par][o + LOFF]);
            }
            float inv = 1.0f/(ipn + 1e-7f);
            c0[i*128 + d] = a0*inv;
            c1[i*128 + d] = a2*inv;
            hwr1(h0h, i, d, a1*inv);
            hwr1(h1h, i, d, a3*inv);
            if (d == 0) ips[i] = ipn;
        }
        __syncthreads();
    }

    asm volatile("cp.async.wait_group 0;":::"memory");

    for (int v = tid; v < 32*128; v += 512){
        int row = v >> 7, d = v & 127;
        size_t o = (size_t)(cell0 + row)*128 + d;
        g_c_st[o]        = c0[row*128 + d];
        g_c_st[o + LOFF] = c1[row*128 + d];
        g_h_st[o]        = hrd1(h0h, row, d);
        g_h_st[o + LOFF] = hrd1(h1h, row, d);
    }
}

// ==================== xw precompute (fp16 2-pass A, 1-pass W) ====================
__global__ void __launch_bounds__(256,1) xwgemm()
{
    extern __shared__ char smem[];
    const uint32_t BUF0 = (smem_u32(smem) + 127u) & ~127u;
    float* Z = (float*)(smem + (BUF0 - smem_u32(smem)));
    const int tid = threadIdx.x, lane = tid & 31, wid = tid >> 5;
    const int mw = wid & 3, nw = wid >> 2;
    const int rowbase = blockIdx.x * 128, nt = blockIdx.y;

    auto load_chunk = [&](int c){
        const uint32_t b = BUF0 + (uint32_t)(c & 1) * 49152u;
        const int kbase = c * 64;
        #pragma unroll
        for (int i = 0; i < 4; ++i){
            int u = tid + i * 256;
            int row = u >> 3, col16 = u & 7;
            uint32_t sw = (uint32_t)(row * 128 + ((col16 ^ (row & 7)) * 16));
            int kg = kbase + col16 * 8;
            size_t o = (size_t)(rowbase + row) * 128 + kg;
            CPA16(b + sw,         g_embf_h + o);
            CPA16(b + 16384 + sw, g_embf_l + o);
            size_t wo = (size_t)(nt * 128 + row) * 128 + kg;
            CPA16(b + 32768 + sw, g_w0xf + wo);
        }
        CP_COMMIT();
    };

    float acc[2][8][4];
    #pragma unroll
    for (int mt=0;mt<2;++mt)
        #pragma unroll
        for (int n8=0;n8<8;++n8)
            #pragma unroll
            for (int e=0;e<4;++e) acc[mt][n8][e]=0.f;

    const int arow = mw * 32 + (lane & 15);
    const uint32_t arbase = (uint32_t)(arow * 128);
    const uint32_t axr = (uint32_t)((arow & 7) << 4);
    const uint32_t acolh = (uint32_t)((lane >> 4) * 16);
    const int brow = nw * 64 + (lane & 7);
    const uint32_t bcolh = (uint32_t)(((lane >> 3) & 1) * 16);

    load_chunk(0);
    #pragma unroll
    for (int c = 0; c < 2; ++c){
        if (c + 1 < 2) load_chunk(c + 1);
        if (c + 1 < 2) asm volatile("cp.async.wait_group 1;":::"memory");
        else           asm volatile("cp.async.wait_group 0;":::"memory");
        __syncthreads();
        const uint32_t b = BUF0 + (uint32_t)(c & 1) * 49152u;
        #pragma unroll
        for (int kk = 0; kk < 4; ++kk){
            uint32_t ah[2][4], al[2][4];
            #pragma unroll
            for (int mt = 0; mt < 2; ++mt){
                uint32_t off = (uint32_t)(mt * 16 * 128) + arbase + (((uint32_t)(kk * 32) + acolh) ^ axr);
                ldmx4(ah[mt], b + off);
                ldmx4(al[mt], b + 16384 + off);
            }
            uint32_t bh[8][2];
            #pragma unroll
            for (int n8 = 0; n8 < 8; ++n8){
                int r = brow + n8 * 8;
                uint32_t off = (uint32_t)(r * 128) + (((uint32_t)(kk * 32) + bcolh) ^ ((uint32_t)((r & 7) << 4)));
                ldmx2(bh[n8], b + 32768 + off);
            }
            #pragma unroll
            for (int mt = 0; mt < 2; ++mt)
                #pragma unroll
                for (int n8 = 0; n8 < 8; ++n8) mmaf16(acc[mt][n8], ah[mt], bh[n8]);
            #pragma unroll
            for (int mt = 0; mt < 2; ++mt)
                #pragma unroll
                for (int n8 = 0; n8 < 8; ++n8) mmaf16(acc[mt][n8], al[mt], bh[n8]);
        }
        __syncthreads();
    }
    {
        const int qr = lane >> 2, qc = (lane & 3) * 2;
        #pragma unroll
        for (int mt = 0; mt < 2; ++mt){
            int r0 = mw * 32 + mt * 16 + qr;
            #pragma unroll
            for (int n8 = 0; n8 < 8; ++n8){
                int c0i = nw * 64 + n8 * 8 + qc;
                Z[r0 * ZSTR + c0i]           = acc[mt][n8][0];
                Z[r0 * ZSTR + c0i + 1]       = acc[mt][n8][1];
                Z[(r0 + 8) * ZSTR + c0i]     = acc[mt][n8][2];
                Z[(r0 + 8) * ZSTR + c0i + 1] = acc[mt][n8][3];
            }
        }
    }
    __syncthreads();
    // store to gate-interleaved xw layout: [ct][d*4 + gate]
    const int row = tid >> 1;
    const int ct = rowbase + row;
    const int cb = (tid & 1) * 64;
    #pragma unroll
    for (int q = 0; q < 64; ++q){
        int pg = nt*128 + cb + q;            // permuted col (block permutation)
        int g  = (pg >> 5) & 3;
        int d  = (pg >> 7) * 32 + (pg & 31);
        g_xw[(size_t)ct*512 + d*4 + g] = Z[row * ZSTR + cb + q];
    }
}

// ==================== fused setup kernel ====================
__global__ void setup_kernel(const int* __restrict__ data, const float* __restrict__ embed,
                             const float* __restrict__ Wi, const float* __restrict__ Wh,
                             const int* __restrict__ tb, const int* __restrict__ fb)
{
    const int bx = blockIdx.x, tid = threadIdx.x;
    if (bx < NB){
        // ---- CSR build ----
        int b = bx, dst = tid;
        __shared__ int stb[NN], sfb[NN], ps[NN];
        stb[dst] = tb[b*NN+dst]; sfb[dst] = fb[b*NN+dst];
        __syncthreads();
        int cnt = 0;
        for (int ss = 0; ss < NN; ++ss) cnt += (stb[ss]==dst) + (sfb[ss]==dst);
        ps[dst] = cnt; __syncthreads();
        for (int o2 = 1; o2 < NN; o2 <<= 1){
            int v = (dst >= o2) ? ps[dst-o2] : 0;
            __syncthreads();
            ps[dst] += v;
            __syncthreads();
        }
        int start = ps[dst] - cnt;
        g_csr_off[b*NN + dst] = b*2*NN + start;
        int p = b*2*NN + start;
        for (int ss = 0; ss < NN; ++ss) if (stb[ss]==dst) g_csr_ent[p++] = ss;
        for (int ss = 0; ss < NN; ++ss) if (sfb[ss]==dst) g_csr_ent[p++] = ss | (int)0x80000000;
    } else if (bx < NB + 512){
        // ---- weight conversion ----
        int i = (bx - NB)*256 + tid;
        if (i < 512*128){
            int p = i>>7, k = i&127;
            int ntc = p>>7, c = p&127, g = c>>5, j = c&31;
            int orig = g*128 + ntc*32 + j;
            g_w0xf[i] = __float2half(Wi[(size_t)k*512+orig]);
        }
        if (i < 512*128){
            int p = i>>7, k = i&127;
            int d = (p>>6)*16 + (p&15), g = (p>>4)&3;
            int orig = g*128 + d;
            g_w0t[i] = __float2half(Wh[(size_t)k*512 + orig]);
        }
        if (i < 512*256){
            int p = i>>8, k = i&255;
            int d = (p>>6)*16 + (p&15), g = (p>>4)&3;
            int orig = g*128 + d;
            float v = (k<128) ? Wi[(size_t)(128+k)*512+orig] : Wh[(size_t)(128+(k-128))*512+orig];
            g_w1t[i] = __float2half(v);
        }
    } else {
        // ---- embedding gather ----
        int i = (bx - NB - 512)*256 + tid;
        if (i < CELLS*NT*HD){
            float v = embed[(size_t)data[i>>7]*HD + (i&127)];
            f16 h = __float2half(v);
            g_embf_h[i] = h; g_embf_l[i] = __float2half(v - __half2float(h));
        }
    }
}

// ==================== final projection: k-split, grid (NB, 8), 512 thr ====================
__global__ void __launch_bounds__(512) final_kernel(
    const int* __restrict__ exi,
    const float* __restrict__ Wo, const float* __restrict__ bo,
    float* __restrict__ out)
{
    int b = blockIdx.x;
    __shared__ float f[4*HD];
    __shared__ float partial[4][128];
    int cell = b*NN + exi[b];
    for (int i = threadIdx.x; i < 4*HD; i += blockDim.x){
        int l = i>>8, ch = (i>>7)&1, d = i&127;
        const float* src = ch ? g_h_st : g_c_st;
        f[i] = src[(size_t)l*LOFF + (size_t)cell*HD + d];
    }
    __syncthreads();

    const int ol = threadIdx.x & 127;          // output within chunk
    const int ks = threadIdx.x >> 7;           // k-segment 0..3
    const int o  = blockIdx.y * 128 + ol;
    float acc = 0.f;
    if (o < OUTV){
        const float* wp = Wo + (size_t)(ks*128) * OUTV + o;
        const float* fp = f + ks*128;
        #pragma unroll 16
        for (int k = 0; k < 128; ++k)
            acc += fp[k] * __ldg(wp + (size_t)k * OUTV);
    }
    partial[ks][ol] = acc;
    __syncthreads();
    if (ks == 0 && o < OUTV){
        float r = partial[0][ol] + partial[1][ol] + partial[2][ol] + partial[3][ol]
                + __ldg(bo + o);
        out[(size_t)b*OUTV + o] = r;
    }
}

// ==================== host ====================
#define TSMEM_XW (98304 + 128)

extern "C" void kernel_launch(void* const* d_in, const int* in_sizes, int n_in,
                              void* d_out, int out_size)
{
    const int*   data  = (const int*)  d_in[0];
    const int*   tb    = (const int*)  d_in[1];
    const int*   fb    = (const int*)  d_in[2];
    const int*   exi   = (const int*)  d_in[3];
    const int*   steps = (const int*)  d_in[4];
    const float* embed = (const float*)d_in[5];
    const float* Wi    = (const float*)d_in[6];
    const float* Wh    = (const float*)d_in[7];
    const float* bl    = (const float*)d_in[8];
    const float* Wb    = (const float*)d_in[9];
    const float* bb    = (const float*)d_in[10];
    const float* Wo    = (const float*)d_in[11];
    const float* bo    = (const float*)d_in[12];
    float* out = (float*)d_out;

    unsigned *bctr, *bgen;
    cudaGetSymbolAddress((void**)&bctr, g_bctr);
    cudaGetSymbolAddress((void**)&bgen, g_bgen);

    cudaFuncSetAttribute(persist, cudaFuncAttributeMaxDynamicSharedMemorySize, SM_NEED);
    cudaFuncSetAttribute(xwgemm,  cudaFuncAttributeMaxDynamicSharedMemorySize, TSMEM_XW);

    cudaMemsetAsync(bctr, 0, sizeof(unsigned)*NB, 0);
    cudaMemsetAsync(bgen, 0, sizeof(unsigned)*NB, 0);

    const int gather_blocks = (CELLS*NT*HD + 255)/256;     // 8192
    setup_kernel<<<NB + 512 + gather_blocks, 256>>>(data, embed, Wi, Wh, tb, fb);

    xwgemm<<<dim3(CELLS*NT/128, 4), 256, TSMEM_XW>>>();

    persist<<<NCTA, 512, SM_NEED>>>(exi, steps, bl, Wb, bb);

    final_kernel<<<dim3(NB, 8), 512>>>(exi, Wo, bo, out);
}

// round 13
// speedup vs baseline: 1.0342x; 1.0342x over previous
#include <cuda_runtime.h>
#include <cuda_fp16.h>
#include <cstdint>
#include <cstddef>

#define NB     16
#define NN     256
#define NT     4
#define HD     128
#define NL     2
#define CELLS  (NB*NN)
#define LOFF   (CELLS*HD)
#define MAXST  15
#define OUTV   1000
#define NCTA   128
#define ZSTR   132

typedef __half f16;

// ---------------- device scratch ----------------
__device__ float g_pubC [2][NL*CELLS*HD];
__device__ float g_pubH [2][NL*CELLS*HD];
__device__ float g_fin  [NB][512];
__device__ f16   g_embf_h[CELLS*NT*HD];
__device__ f16   g_embf_l[CELLS*NT*HD];
__device__ float g_xw   [CELLS*NT*512];    // layout: [cell*4+t][d*4+gate]
__device__ f16   g_w0xf [512*128];         // Wi(l0)^T, block permutation, fp16
__device__ f16   g_w0t  [512*128];         // Wh0^T, interleaved permutation, fp16
__device__ f16   g_w1t  [512*256];         // [Wi1;Wh1]^T, interleaved permutation, fp16
__device__ float g_wtb[2][CELLS], g_wfb[2][CELLS];
__device__ int   g_csr_off[NB*NN];
__device__ int   g_csr_ent[NB*NN*2];
__device__ unsigned g_bctr[NB];
__device__ unsigned g_bgen[NB];

__device__ __forceinline__ float tanhap(float x){
    float r; asm("tanh.approx.f32 %0, %1;" : "=f"(r) : "f"(x)); return r;
}
__device__ __forceinline__ float sigf(float x){ return fmaf(tanhap(0.5f*x), 0.5f, 0.5f); }

__device__ __forceinline__ uint32_t smem_u32(const void* p){
    uint32_t a; asm("{ .reg .u64 t; cvta.to.shared.u64 t, %1; cvt.u32.u64 %0, t; }":"=r"(a):"l"(p)); return a;
}
#define CPA16(d,s) asm volatile("cp.async.cg.shared.global [%0], [%1], 16;"::"r"(d),"l"((unsigned long long)__cvta_generic_to_global((const void*)(s))):"memory")
#define CP_COMMIT() asm volatile("cp.async.commit_group;":::"memory")

__device__ __forceinline__ void ldmx4(uint32_t* r, uint32_t a){
    asm volatile("ldmatrix.sync.aligned.m8n8.x4.shared.b16 {%0,%1,%2,%3}, [%4];"
        : "=r"(r[0]),"=r"(r[1]),"=r"(r[2]),"=r"(r[3]) : "r"(a));
}
__device__ __forceinline__ void ldmx2(uint32_t* r, uint32_t a){
    asm volatile("ldmatrix.sync.aligned.m8n8.x2.shared.b16 {%0,%1}, [%2];"
        : "=r"(r[0]),"=r"(r[1]) : "r"(a));
}
__device__ __forceinline__ void mmaf16(float* d, const uint32_t* a, const uint32_t* b){
    asm volatile("mma.sync.aligned.m16n8k16.row.col.f32.f16.f16.f32 "
        "{%0,%1,%2,%3}, {%4,%5,%6,%7}, {%8,%9}, {%0,%1,%2,%3};"
        : "+f"(d[0]),"+f"(d[1]),"+f"(d[2]),"+f"(d[3])
        : "r"(a[0]),"r"(a[1]),"r"(a[2]),"r"(a[3]),"r"(b[0]),"r"(b[1]));
}

__device__ __forceinline__ void batchsync(int b, unsigned &cnt){
    __syncthreads();
    if (threadIdx.x == 0){
        __threadfence();
        unsigned t = ++cnt;
        if (atomicAdd(&g_bctr[b], 1u) == 7u){
            atomicExch(&g_bctr[b], 0u);
            __threadfence();
            *(volatile unsigned*)&g_bgen[b] = t;
        } else {
            while (*(volatile unsigned*)&g_bgen[b] < t) __nanosleep(32);
        }
        __threadfence();
    }
    __syncthreads();
}

// smem layout (bytes, from 1KB-aligned base)
#define SW_OFF   0u          // W double buffer: 2 x 65536
#define H0H_OFF  131072u
#define H1H_OFF  139264u
#define C0_OFF   147456u
#define C1_OFF   163840u
#define SNAP_OFF 180224u
#define SWT_OFF  182272u
#define SWF_OFF  183296u
#define IP_OFF   184320u
#define WBS_OFF  184448u
#define BLS_OFF  188544u
#define SM_NEED  (192640u + 1024u)

__device__ __forceinline__ float hrd1(const char* hh, int row, int d){
    uint32_t off = (uint32_t)(row*256) + ((uint32_t)((d>>3) ^ (row&7))<<4) + (uint32_t)((d&7)*2);
    return __half2float(*(const f16*)(hh+off));
}
__device__ __forceinline__ void hwr1(char* hh, int row, int d, float v){
    uint32_t off = (uint32_t)(row*256) + ((uint32_t)((d>>3) ^ (row&7))<<4) + (uint32_t)((d&7)*2);
    *(f16*)(hh+off) = __float2half(v);
}

// ==================== persistent kernel ====================
__global__ __launch_bounds__(512,1) void persist(
    const int* __restrict__ exi, const int* __restrict__ steps,
    const float* __restrict__ bl, const float* __restrict__ Wb,
    const float* __restrict__ bb,
    const float* __restrict__ Wo, const float* __restrict__ bo,
    float* __restrict__ out)
{
    extern __shared__ char dsm[];
    const uint32_t S0 = smem_u32(dsm);
    const uint32_t S  = (S0 + 1023u) & ~1023u;
    char* base = dsm + (S - S0);
    char* h0h = base + H0H_OFF;
    char* h1h = base + H1H_OFF;
    float* c0 = (float*)(base + C0_OFF);
    float* c1 = (float*)(base + C1_OFF);
    float* snC0 = (float*)(base + SNAP_OFF);
    float* snC1 = snC0 + 128; float* snH0 = snC0 + 256; float* snH1 = snC0 + 384;
    float* swt = (float*)(base + SWT_OFF);
    float* swf = (float*)(base + SWF_OFF);
    float* ips = (float*)(base + IP_OFF);
    float* wbs = (float*)(base + WBS_OFF);
    float* bls = (float*)(base + BLS_OFF);

    const int tid = threadIdx.x, lane = tid & 31, wid = tid >> 5;
    const int bid = blockIdx.x;
    const int b = bid >> 3, cell0 = bid * 32, lb = (bid & 7) * 32;
    const int mw = wid & 1, nw = wid >> 1;
    const int qr = lane >> 2, qc = (lane & 3) * 2;

    int wpar = 0;
    auto pref = [&](const f16* src, int KK, int buf){
        uint32_t dst = S + SW_OFF + (uint32_t)buf*65536u;
        #pragma unroll
        for (int i = 0; i < 8; ++i){
            int idx = tid + i*512;
            int row = idx >> 3, c16 = idx & 7;
            CPA16(dst + (uint32_t)(row*128) + ((uint32_t)(c16 ^ (row&7))<<4),
                  src + (size_t)row*KK + c16*8);
        }
        CP_COMMIT();
    };

    pref(g_w0t, 128, 0);   // kick off continuous W pipeline

    // init state
    for (int i = tid; i < 2048; i += 512){
        ((uint32_t*)h0h)[i] = 0; ((uint32_t*)h1h)[i] = 0;
    }
    for (int i = tid; i < 4096; i += 512){ c0[i] = 0.f; c1[i] = 0.f; }
    if (tid < 32) ips[tid] = (cell0 + tid == b*256) ? 1.0f : 0.0f;
    for (int i = tid; i < 1024; i += 512){ wbs[i] = __ldg(Wb + i); bls[i] = __ldg(bl + i); }
    __syncthreads();

    const int el = __ldg(exi + b);
    const bool owned = (el >> 5) == (bid & 7);
    const int eloc = el & 31;
    const int nsteps = __ldg(steps + b);
    const float bb0 = __ldg(bb), bb1 = __ldg(bb + 1);

    // fused GEMM (M=32,N=512) + LSTM epilogue; continuous W pipeline
    auto gemm = [&](int nslab, const f16* wsrc, int KK,
                    const f16* nextw, int nextKK,
                    const char* aHi0, const char* aHi1,
                    const float* xwp, const float* bias,
                    float* cbuf, char* hOh)
    {
        float acc[8][4];
        #pragma unroll
        for (int n8=0;n8<8;++n8){ acc[n8][0]=0.f; acc[n8][1]=0.f; acc[n8][2]=0.f; acc[n8][3]=0.f; }

        for (int s = 0; s < nslab; ++s){
            asm volatile("cp.async.wait_group 0;":::"memory");
            __syncthreads();
            if (s + 1 < nslab) pref(wsrc + (s+1)*64, KK, wpar^1);
            else               pref(nextw, nextKK, wpar^1);
            uint32_t wb = S + SW_OFF + (uint32_t)wpar*65536u;
            #pragma unroll
            for (int kk = 0; kk < 4; ++kk){
                int kglob = s*64 + kk*16;
                const char* ah; int kr;
                if (kglob < 128){ ah = aHi0; kr = kglob; }
                else            { ah = aHi1; kr = kglob - 128; }
                int row = mw*16 + (lane & 15);
                uint32_t u = (uint32_t)(((kr >> 3) + (lane >> 4)) ^ (row & 7));
                uint32_t Ah[4];
                ldmx4(Ah, smem_u32(ah) + (uint32_t)(row*256) + (u << 4));
                uint32_t B[4][4];
                #pragma unroll
                for (int p = 0; p < 4; ++p){
                    int r = nw*64 + p*16 + ((lane >> 4) << 3) + (lane & 7);
                    uint32_t kh = (uint32_t)(kk*2 + ((lane >> 3) & 1));
                    ldmx4(B[p], wb + (uint32_t)(r*128) + ((kh ^ (uint32_t)(r & 7)) << 4));
                }
                #pragma unroll
                for (int p = 0; p < 4; ++p){
                    mmaf16(acc[2*p],   Ah, &B[p][0]);
                    mmaf16(acc[2*p+1], Ah, &B[p][2]);
                }
            }
            wpar ^= 1;
        }
        __syncthreads();

        // epilogue: register gate math; xw loaded as one float4 per output
        #pragma unroll
        for (int rh = 0; rh < 2; ++rh){
            int row = mw*16 + qr + rh*8;
            int cell = cell0 + row;
            const float4* xr4 = xwp ? (const float4*)(xwp + (size_t)cell*2048) : nullptr;
            #pragma unroll
            for (int dd = 0; dd < 4; ++dd){
                int dlow = qc + (dd & 1) + (dd >> 1)*8;
                int hb = dd >> 1;
                int e = (dd & 1) + rh*2;
                int d = nw*16 + dlow;
                float vi = acc[hb][e]     + bias[d];
                float vf = acc[2+hb][e]   + bias[128 + d];
                float vg = acc[4+hb][e]   + bias[256 + d];
                float vo = acc[6+hb][e]   + bias[384 + d];
                if (xr4){
                    float4 xv = __ldg(xr4 + d);
                    vi += xv.x; vf += xv.y; vg += xv.z; vo += xv.w;
                }
                float cold = cbuf[row*128 + d];
                float c2 = sigf(vf)*cold + sigf(vi)*tanhap(vg);
                float hv = sigf(vo)*tanhap(c2);
                cbuf[row*128 + d] = c2;
                hwr1(hOh, row, d, hv);
            }
        }
        __syncthreads();
    };

    unsigned scnt = 0;
    for (int s = 0; s < nsteps; ++s){
        int par = s & 1;

        if (owned){
            int a = tid >> 7, d = tid & 127;
            if (a == 0) snC0[d] = c0[eloc*128 + d];
            else if (a == 1) snC1[d] = c1[eloc*128 + d];
            else if (a == 2) snH0[d] = hrd1(h0h, eloc, d);
            else             snH1[d] = hrd1(h1h, eloc, d);
        }
        __syncthreads();

        for (int t = 0; t < NT; ++t){
            gemm(2, g_w0t, 128, g_w1t, 256, h0h, h0h, g_xw + t*512, bls,       c0, h0h);
            gemm(4, g_w1t, 256, g_w0t, 128, h0h, h1h, nullptr,      bls + 512, c1, h1h);
        }

        if (owned){
            int a = tid >> 7, d = tid & 127;
            if (a == 0) c0[eloc*128 + d] = snC0[d];
            else if (a == 1) c1[eloc*128 + d] = snC1[d];
            else if (a == 2) hwr1(h0h, eloc, d, snH0[d]);
            else             hwr1(h1h, eloc, d, snH1[d]);
        }
        __syncthreads();

        // branch + publish
        {
            #pragma unroll
            for (int q = 0; q < 2; ++q){
                int i = wid*2 + q;
                float a0 = 0.f, a1 = 0.f;
                for (int d = lane; d < 128; d += 32){
                    float v0 = c0[i*128 + d];
                    float v1 = hrd1(h0h, i, d);
                    float v2 = c1[i*128 + d];
                    float v3 = hrd1(h1h, i, d);
                    a0 += v0*wbs[2*d]        + v1*wbs[2*(128+d)]
                        + v2*wbs[2*(256+d)]  + v3*wbs[2*(384+d)];
                    a1 += v0*wbs[2*d+1]      + v1*wbs[2*(128+d)+1]
                        + v2*wbs[2*(256+d)+1]+ v3*wbs[2*(384+d)+1];
                }
                #pragma unroll
                for (int o2 = 16; o2; o2 >>= 1){
                    a0 += __shfl_xor_sync(~0u, a0, o2);
                    a1 += __shfl_xor_sync(~0u, a1, o2);
                }
                if (lane == 0){
                    a0 += bb0; a1 += bb1;
                    float m = fmaxf(a0, a1), e0 = __expf(a0-m), e1 = __expf(a1-m);
                    float inv = 1.0f/(e0+e1), w = ips[i];
                    g_wtb[par][cell0 + i] = e0*inv*w;
                    g_wfb[par][cell0 + i] = e1*inv*w;
                }
            }
            for (int v = tid; v < 32*128; v += 512){
                int row = v >> 7, d = v & 127;
                size_t o = (size_t)(cell0 + row)*128 + d;
                g_pubC[par][o]        = c0[row*128 + d];
                g_pubC[par][o + LOFF] = c1[row*128 + d];
                g_pubH[par][o]        = hrd1(h0h, row, d);
                g_pubH[par][o + LOFF] = hrd1(h1h, row, d);
            }
        }
        batchsync(b, scnt);

        // aggregation (CSR)
        for (int i = tid; i < 256; i += 512){
            swt[i] = __ldcg(&g_wtb[par][b*256 + i]);
            swf[i] = __ldcg(&g_wfb[par][b*256 + i]);
        }
        __syncthreads();
        #pragma unroll
        for (int it = 0; it < 8; ++it){
            int i = it*4 + (tid >> 7);
            int d = tid & 127;
            int dstb = lb + i;
            int o0 = g_csr_off[b*NN + dstb];
            int o1 = (dstb == NN-1) ? (b*2*NN + 2*NN) : g_csr_off[b*NN + dstb + 1];
            float a0=0.f, a1=0.f, a2=0.f, a3=0.f, ipn=0.f;
            for (int qq = o0; qq < o1; ++qq){
                int v = g_csr_ent[qq];
                int src = v & 255;
                float w = (v < 0) ? swf[src] : swt[src];
                ipn += w;
                size_t o = (size_t)(b*256 + src)*128 + d;
                a0 += w * __ldcg(&g_pubC[par][o]);
                a1 += w * __ldcg(&g_pubH[par][o]);
                a2 += w * __ldcg(&g_pubC[par][o + LOFF]);
                a3 += w * __ldcg(&g_pubH[par][o + LOFF]);
            }
            float inv = 1.0f/(ipn + 1e-7f);
            c0[i*128 + d] = a0*inv;
            c1[i*128 + d] = a2*inv;
            hwr1(h0h, i, d, a1*inv);
            hwr1(h1h, i, d, a3*inv);
            if (d == 0) ips[i] = ipn;
        }
        __syncthreads();
    }

    asm volatile("cp.async.wait_group 0;":::"memory");

    // ---- fused output projection (overlaps across batches) ----
    // owner publishes exit-cell features f = [c0, h0, c1, h1]
    if (owned){
        int a = tid >> 7, d = tid & 127;
        float v;
        if (a == 0)      v = c0[eloc*128 + d];
        else if (a == 1) v = hrd1(h0h, eloc, d);
        else if (a == 2) v = c1[eloc*128 + d];
        else             v = hrd1(h1h, eloc, d);
        g_fin[b][a*128 + d] = v;
    }
    batchsync(b, scnt);

    {
        float* f = (float*)(base + SNAP_OFF);          // reuse snapshot area (512 floats)
        float* partial = (float*)(base + WBS_OFF);     // reuse wbs area (512 floats)
        for (int i = tid; i < 512; i += 512) f[i] = __ldcg(&g_fin[b][i]);
        __syncthreads();
        const int ol = tid & 127;
        const int ks = tid >> 7;
        const int o  = (bid & 7) * 128 + ol;
        float acc = 0.f;
        if (o < OUTV){
            const float* wp = Wo + (size_t)(ks*128) * OUTV + o;
            const float* fp = f + ks*128;
            #pragma unroll 16
            for (int k = 0; k < 128; ++k)
                acc += fp[k] * __ldg(wp + (size_t)k * OUTV);
        }
        partial[ks*128 + ol] = acc;
        __syncthreads();
        if (ks == 0 && o < OUTV){
            float r = partial[ol] + partial[128 + ol] + partial[256 + ol] + partial[384 + ol]
                    + __ldg(bo + o);
            out[(size_t)b*OUTV + o] = r;
        }
    }
}

// ==================== xw precompute (fp16 2-pass A, 1-pass W) ====================
__global__ void __launch_bounds__(256,1) xwgemm()
{
    extern __shared__ char smem[];
    const uint32_t BUF0 = (smem_u32(smem) + 127u) & ~127u;
    float* Z = (float*)(smem + (BUF0 - smem_u32(smem)));
    const int tid = threadIdx.x, lane = tid & 31, wid = tid >> 5;
    const int mw = wid & 3, nw = wid >> 2;
    const int rowbase = blockIdx.x * 128, nt = blockIdx.y;

    auto load_chunk = [&](int c){
        const uint32_t b = BUF0 + (uint32_t)(c & 1) * 49152u;
        const int kbase = c * 64;
        #pragma unroll
        for (int i = 0; i < 4; ++i){
            int u = tid + i * 256;
            int row = u >> 3, col16 = u & 7;
            uint32_t sw = (uint32_t)(row * 128 + ((col16 ^ (row & 7)) * 16));
            int kg = kbase + col16 * 8;
            size_t o = (size_t)(rowbase + row) * 128 + kg;
            CPA16(b + sw,         g_embf_h + o);
            CPA16(b + 16384 + sw, g_embf_l + o);
            size_t wo = (size_t)(nt * 128 + row) * 128 + kg;
            CPA16(b + 32768 + sw, g_w0xf + wo);
        }
        CP_COMMIT();
    };

    float acc[2][8][4];
    #pragma unroll
    for (int mt=0;mt<2;++mt)
        #pragma unroll
        for (int n8=0;n8<8;++n8)
            #pragma unroll
            for (int e=0;e<4;++e) acc[mt][n8][e]=0.f;

    const int arow = mw * 32 + (lane & 15);
    const uint32_t arbase = (uint32_t)(arow * 128);
    const uint32_t axr = (uint32_t)((arow & 7) << 4);
    const uint32_t acolh = (uint32_t)((lane >> 4) * 16);
    const int brow = nw * 64 + (lane & 7);
    const uint32_t bcolh = (uint32_t)(((lane >> 3) & 1) * 16);

    load_chunk(0);
    #pragma unroll
    for (int c = 0; c < 2; ++c){
        if (c + 1 < 2) load_chunk(c + 1);
        if (c + 1 < 2) asm volatile("cp.async.wait_group 1;":::"memory");
        else           asm volatile("cp.async.wait_group 0;":::"memory");
        __syncthreads();
        const uint32_t b = BUF0 + (uint32_t)(c & 1) * 49152u;
        #pragma unroll
        for (int kk = 0; kk < 4; ++kk){
            uint32_t ah[2][4], al[2][4];
            #pragma unroll
            for (int mt = 0; mt < 2; ++mt){
                uint32_t off = (uint32_t)(mt * 16 * 128) + arbase + (((uint32_t)(kk * 32) + acolh) ^ axr);
                ldmx4(ah[mt], b + off);
                ldmx4(al[mt], b + 16384 + off);
            }
            uint32_t bh[8][2];
            #pragma unroll
            for (int n8 = 0; n8 < 8; ++n8){
                int r = brow + n8 * 8;
                uint32_t off = (uint32_t)(r * 128) + (((uint32_t)(kk * 32) + bcolh) ^ ((uint32_t)((r & 7) << 4)));
                ldmx2(bh[n8], b + 32768 + off);
            }
            #pragma unroll
            for (int mt = 0; mt < 2; ++mt)
                #pragma unroll
                for (int n8 = 0; n8 < 8; ++n8) mmaf16(acc[mt][n8], ah[mt], bh[n8]);
            #pragma unroll
            for (int mt = 0; mt < 2; ++mt)
                #pragma unroll
                for (int n8 = 0; n8 < 8; ++n8) mmaf16(acc[mt][n8], al[mt], bh[n8]);
        }
        __syncthreads();
    }
    {
        const int qr = lane >> 2, qc = (lane & 3) * 2;
        #pragma unroll
        for (int mt = 0; mt < 2; ++mt){
            int r0 = mw * 32 + mt * 16 + qr;
            #pragma unroll
            for (int n8 = 0; n8 < 8; ++n8){
                int c0i = nw * 64 + n8 * 8 + qc;
                Z[r0 * ZSTR + c0i]           = acc[mt][n8][0];
                Z[r0 * ZSTR + c0i + 1]       = acc[mt][n8][1];
                Z[(r0 + 8) * ZSTR + c0i]     = acc[mt][n8][2];
                Z[(r0 + 8) * ZSTR + c0i + 1] = acc[mt][n8][3];
            }
        }
    }
    __syncthreads();
    // store to gate-interleaved xw layout: [ct][d*4 + gate]
    const int row = tid >> 1;
    const int ct = rowbase + row;
    const int cb = (tid & 1) * 64;
    #pragma unroll
    for (int q = 0; q < 64; ++q){
        int pg = nt*128 + cb + q;            // permuted col (block permutation)
        int g  = (pg >> 5) & 3;
        int d  = (pg >> 7) * 32 + (pg & 31);
        g_xw[(size_t)ct*512 + d*4 + g] = Z[row * ZSTR + cb + q];
    }
}

// ==================== fused setup kernel ====================
__global__ void setup_kernel(const int* __restrict__ data, const float* __restrict__ embed,
                             const float* __restrict__ Wi, const float* __restrict__ Wh,
                             const int* __restrict__ tb, const int* __restrict__ fb)
{
    const int bx = blockIdx.x, tid = threadIdx.x;
    if (bx < NB){
        // ---- CSR build ----
        int b = bx, dst = tid;
        __shared__ int stb[NN], sfb[NN], ps[NN];
        stb[dst] = tb[b*NN+dst]; sfb[dst] = fb[b*NN+dst];
        __syncthreads();
        int cnt = 0;
        for (int ss = 0; ss < NN; ++ss) cnt += (stb[ss]==dst) + (sfb[ss]==dst);
        ps[dst] = cnt; __syncthreads();
        for (int o2 = 1; o2 < NN; o2 <<= 1){
            int v = (dst >= o2) ? ps[dst-o2] : 0;
            __syncthreads();
            ps[dst] += v;
            __syncthreads();
        }
        int start = ps[dst] - cnt;
        g_csr_off[b*NN + dst] = b*2*NN + start;
        int p = b*2*NN + start;
        for (int ss = 0; ss < NN; ++ss) if (stb[ss]==dst) g_csr_ent[p++] = ss;
        for (int ss = 0; ss < NN; ++ss) if (sfb[ss]==dst) g_csr_ent[p++] = ss | (int)0x80000000;
    } else if (bx < NB + 512){
        // ---- weight conversion ----
        int i = (bx - NB)*256 + tid;
        if (i < 512*128){
            int p = i>>7, k = i&127;
            int ntc = p>>7, c = p&127, g = c>>5, j = c&31;
            int orig = g*128 + ntc*32 + j;
            g_w0xf[i] = __float2half(Wi[(size_t)k*512+orig]);
        }
        if (i < 512*128){
            int p = i>>7, k = i&127;
            int d = (p>>6)*16 + (p&15), g = (p>>4)&3;
            int orig = g*128 + d;
            g_w0t[i] = __float2half(Wh[(size_t)k*512 + orig]);
        }
        if (i < 512*256){
            int p = i>>8, k = i&255;
            int d = (p>>6)*16 + (p&15), g = (p>>4)&3;
            int orig = g*128 + d;
            float v = (k<128) ? Wi[(size_t)(128+k)*512+orig] : Wh[(size_t)(128+(k-128))*512+orig];
            g_w1t[i] = __float2half(v);
        }
    } else {
        // ---- embedding gather ----
        int i = (bx - NB - 512)*256 + tid;
        if (i < CELLS*NT*HD){
            float v = embed[(size_t)data[i>>7]*HD + (i&127)];
            f16 h = __float2half(v);
            g_embf_h[i] = h; g_embf_l[i] = __float2half(v - __half2float(h));
        }
    }
}

// ==================== host ====================
#define TSMEM_XW (98304 + 128)

extern "C" void kernel_launch(void* const* d_in, const int* in_sizes, int n_in,
                              void* d_out, int out_size)
{
    const int*   data  = (const int*)  d_in[0];
    const int*   tb    = (const int*)  d_in[1];
    const int*   fb    = (const int*)  d_in[2];
    const int*   exi   = (const int*)  d_in[3];
    const int*   steps = (const int*)  d_in[4];
    const float* embed = (const float*)d_in[5];
    const float* Wi    = (const float*)d_in[6];
    const float* Wh    = (const float*)d_in[7];
    const float* bl    = (const float*)d_in[8];
    const float* Wb    = (const float*)d_in[9];
    const float* bb    = (const float*)d_in[10];
    const float* Wo    = (const float*)d_in[11];
    const float* bo    = (const float*)d_in[12];
    float* out = (float*)d_out;

    unsigned *bctr, *bgen;
    cudaGetSymbolAddress((void**)&bctr, g_bctr);
    cudaGetSymbolAddress((void**)&bgen, g_bgen);

    cudaFuncSetAttribute(persist, cudaFuncAttributeMaxDynamicSharedMemorySize, SM_NEED);
    cudaFuncSetAttribute(xwgemm,  cudaFuncAttributeMaxDynamicSharedMemorySize, TSMEM_XW);

    cudaMemsetAsync(bctr, 0, sizeof(unsigned)*NB, 0);
    cudaMemsetAsync(bgen, 0, sizeof(unsigned)*NB, 0);

    const int gather_blocks = (CELLS*NT*HD + 255)/256;     // 8192
    setup_kernel<<<NB + 512 + gather_blocks, 256>>>(data, embed, Wi, Wh, tb, fb);

    xwgemm<<<dim3(CELLS*NT/128, 4), 256, TSMEM_XW>>>();

    persist<<<NCTA, 512, SM_NEED>>>(exi, steps, bl, Wb, bb, Wo, bo, out);
}

// round 14
// speedup vs baseline: 1.2756x; 1.2334x over previous
#include <cuda_runtime.h>
#include <cuda_fp16.h>
#include <cstdint>
#include <cstddef>

#define NB     16
#define NN     256
#define NT     4
#define HD     128
#define NL     2
#define CELLS  (NB*NN)
#define LOFF   (CELLS*HD)
#define MAXST  15
#define OUTV   1000
#define NCTA   128
#define ZSTR   132

typedef __half f16;

// ---------------- device scratch ----------------
__device__ float g_pubC [2][NL*CELLS*HD];
__device__ float g_pubH [2][NL*CELLS*HD];
__device__ float g_fin  [NB][512];
__device__ f16   g_embf_h[CELLS*NT*HD];
__device__ f16   g_embf_l[CELLS*NT*HD];
__device__ float g_xw   [CELLS*NT*512];    // layout: [cell*4+t][d*4+gate]
__device__ f16   g_w0xf [512*128];         // Wi(l0)^T, block permutation (xwgemm)
__device__ f16   g_w0t  [512*128];         // Wh0^T, gate-8 permutation, fp16
__device__ f16   g_w1t  [512*256];         // [Wi1;Wh1]^T, gate-8 permutation, fp16
__device__ float g_wtb[2][CELLS], g_wfb[2][CELLS];
__device__ int   g_csr_off[NB*NN];
__device__ int   g_csr_ent[NB*NN*2];
__device__ int   g_slot[8][2];
__device__ unsigned g_bctr[NB];
__device__ unsigned g_bgen[NB];

__device__ __forceinline__ float tanhap(float x){
    float r; asm("tanh.approx.f32 %0, %1;" : "=f"(r) : "f"(x)); return r;
}
__device__ __forceinline__ float sigf(float x){ return fmaf(tanhap(0.5f*x), 0.5f, 0.5f); }

__device__ __forceinline__ uint32_t smem_u32(const void* p){
    uint32_t a; asm("{ .reg .u64 t; cvta.to.shared.u64 t, %1; cvt.u32.u64 %0, t; }":"=r"(a):"l"(p)); return a;
}
#define CPA16(d,s) asm volatile("cp.async.cg.shared.global [%0], [%1], 16;"::"r"(d),"l"((unsigned long long)__cvta_generic_to_global((const void*)(s))):"memory")
#define CP_COMMIT() asm volatile("cp.async.commit_group;":::"memory")

__device__ __forceinline__ void ldmx4(uint32_t* r, uint32_t a){
    asm volatile("ldmatrix.sync.aligned.m8n8.x4.shared.b16 {%0,%1,%2,%3}, [%4];"
        : "=r"(r[0]),"=r"(r[1]),"=r"(r[2]),"=r"(r[3]) : "r"(a));
}
__device__ __forceinline__ void ldmx2(uint32_t* r, uint32_t a){
    asm volatile("ldmatrix.sync.aligned.m8n8.x2.shared.b16 {%0,%1}, [%2];"
        : "=r"(r[0]),"=r"(r[1]) : "r"(a));
}
__device__ __forceinline__ void mmaf16(float* d, const uint32_t* a, const uint32_t* b){
    asm volatile("mma.sync.aligned.m16n8k16.row.col.f32.f16.f16.f32 "
        "{%0,%1,%2,%3}, {%4,%5,%6,%7}, {%8,%9}, {%0,%1,%2,%3};"
        : "+f"(d[0]),"+f"(d[1]),"+f"(d[2]),"+f"(d[3])
        : "r"(a[0]),"r"(a[1]),"r"(a[2]),"r"(a[3]),"r"(b[0]),"r"(b[1]));
}

// per-batch 16-CTA barrier (monotonic generation)
__device__ __forceinline__ void batchsync(int b, unsigned &cnt){
    __syncthreads();
    if (threadIdx.x == 0){
        __threadfence();
        unsigned t = ++cnt;
        if (atomicAdd(&g_bctr[b], 1u) == 15u){
            atomicExch(&g_bctr[b], 0u);
            __threadfence();
            *(volatile unsigned*)&g_bgen[b] = t;
        } else {
            while (*(volatile unsigned*)&g_bgen[b] < t) __nanosleep(32);
        }
        __threadfence();
    }
    __syncthreads();
}

// smem layout (bytes, from 1KB-aligned base). cpc = 16 cells per CTA.
#define SW_OFF   0u          // W double buffer: 2 x 65536
#define H0H_OFF  131072u     // 16*256 = 4096
#define H1H_OFF  135168u     // 4096
#define C0_OFF   139264u     // 8192
#define C1_OFF   147456u     // 8192
#define SNAP_OFF 155648u     // 2048
#define SWT_OFF  157696u     // 1024
#define SWF_OFF  158720u     // 1024
#define IP_OFF   159744u     // 256
#define WBS_OFF  160000u     // 4096
#define BLS_OFF  164096u     // 4096
#define SM_NEED  (168192u + 1024u)

__device__ __forceinline__ float hrd1(const char* hh, int row, int d){
    uint32_t off = (uint32_t)(row*256) + ((uint32_t)((d>>3) ^ (row&7))<<4) + (uint32_t)((d&7)*2);
    return __half2float(*(const f16*)(hh+off));
}
__device__ __forceinline__ void hwr1(char* hh, int row, int d, float v){
    uint32_t off = (uint32_t)(row*256) + ((uint32_t)((d>>3) ^ (row&7))<<4) + (uint32_t)((d&7)*2);
    *(f16*)(hh+off) = __float2half(v);
}

// ==================== persistent kernel: 8 slots x 16 CTAs, 2 batches/slot ====================
__global__ __launch_bounds__(512,1) void persist(
    const int* __restrict__ exi, const int* __restrict__ steps,
    const float* __restrict__ bl, const float* __restrict__ Wb,
    const float* __restrict__ bb,
    const float* __restrict__ Wo, const float* __restrict__ bo,
    float* __restrict__ out)
{
    extern __shared__ char dsm[];
    const uint32_t S0 = smem_u32(dsm);
    const uint32_t S  = (S0 + 1023u) & ~1023u;
    char* base = dsm + (S - S0);
    char* h0h = base + H0H_OFF;
    char* h1h = base + H1H_OFF;
    float* c0 = (float*)(base + C0_OFF);
    float* c1 = (float*)(base + C1_OFF);
    float* snC0 = (float*)(base + SNAP_OFF);
    float* snC1 = snC0 + 128; float* snH0 = snC0 + 256; float* snH1 = snC0 + 384;
    float* swt = (float*)(base + SWT_OFF);
    float* swf = (float*)(base + SWF_OFF);
    float* ips = (float*)(base + IP_OFF);
    float* wbs = (float*)(base + WBS_OFF);
    float* bls = (float*)(base + BLS_OFF);

    const int tid = threadIdx.x, lane = tid & 31, wid = tid >> 5;
    const int bid = blockIdx.x;
    const int slot = bid >> 4, li = bid & 15;
    const int qr = lane >> 2, qc = (lane & 3) * 2;

    int wpar = 0;
    auto pref = [&](const f16* src, int KK, int buf){
        uint32_t dst = S + SW_OFF + (uint32_t)buf*65536u;
        #pragma unroll
        for (int i = 0; i < 8; ++i){
            int idx = tid + i*512;
            int row = idx >> 3, c16 = idx & 7;
            CPA16(dst + (uint32_t)(row*128) + ((uint32_t)(c16 ^ (row&7))<<4),
                  src + (size_t)row*KK + c16*8);
        }
        CP_COMMIT();
    };

    pref(g_w0t, 128, 0);   // kick off continuous W pipeline

    for (int i = tid; i < 1024; i += 512){ wbs[i] = __ldg(Wb + i); bls[i] = __ldg(bl + i); }
    const float bb0 = __ldg(bb), bb1 = __ldg(bb + 1);

    // fused GEMM (M=16, N=512) + LSTM epilogue; continuous W pipeline
    auto gemm = [&](int nslab, const f16* wsrc, int KK,
                    const f16* nextw, int nextKK,
                    const char* aHi0, const char* aHi1,
                    const float* xwp, const float* bias,
                    float* cbuf, char* hOh, int cell0)
    {
        float acc[4][4];
        #pragma unroll
        for (int j=0;j<4;++j){ acc[j][0]=0.f; acc[j][1]=0.f; acc[j][2]=0.f; acc[j][3]=0.f; }

        for (int s = 0; s < nslab; ++s){
            asm volatile("cp.async.wait_group 0;":::"memory");
            __syncthreads();
            if (s + 1 < nslab) pref(wsrc + (s+1)*64, KK, wpar^1);
            else               pref(nextw, nextKK, wpar^1);
            uint32_t wb = S + SW_OFF + (uint32_t)wpar*65536u;
            #pragma unroll
            for (int kk = 0; kk < 4; ++kk){
                int kglob = s*64 + kk*16;
                const char* ah; int kr;
                if (kglob < 128){ ah = aHi0; kr = kglob; }
                else            { ah = aHi1; kr = kglob - 128; }
                int row = lane & 15;
                uint32_t u = (uint32_t)(((kr >> 3) + (lane >> 4)) ^ (row & 7));
                uint32_t Ah[4];
                ldmx4(Ah, smem_u32(ah) + (uint32_t)(row*256) + (u << 4));
                uint32_t B[2][4];
                #pragma unroll
                for (int p = 0; p < 2; ++p){
                    int r = wid*32 + p*16 + ((lane >> 4) << 3) + (lane & 7);
                    uint32_t kh = (uint32_t)(kk*2 + ((lane >> 3) & 1));
                    ldmx4(B[p], wb + (uint32_t)(r*128) + ((kh ^ (uint32_t)(r & 7)) << 4));
                }
                mmaf16(acc[0], Ah, &B[0][0]);
                mmaf16(acc[1], Ah, &B[0][2]);
                mmaf16(acc[2], Ah, &B[1][0]);
                mmaf16(acc[3], Ah, &B[1][2]);
            }
            wpar ^= 1;
        }
        __syncthreads();

        // epilogue: warp wid covers d = wid*8 + 0..7 (gate-8 permutation: acc[g] = gate g)
        #pragma unroll
        for (int e = 0; e < 4; ++e){
            int dl  = qc + (e & 1);
            int row = qr + (e >> 1)*8;
            int d   = wid*8 + dl;
            int cell = cell0 + row;
            float vi = acc[0][e] + bias[d];
            float vf = acc[1][e] + bias[128 + d];
            float vg = acc[2][e] + bias[256 + d];
            float vo = acc[3][e] + bias[384 + d];
            if (xwp){
                float4 xv = __ldg((const float4*)(xwp + (size_t)cell*2048) + d);
                vi += xv.x; vf += xv.y; vg += xv.z; vo += xv.w;
            }
            float cold = cbuf[row*128 + d];
            float c2 = sigf(vf)*cold + sigf(vi)*tanhap(vg);
            float hv = sigf(vo)*tanhap(c2);
            cbuf[row*128 + d] = c2;
            hwr1(hOh, row, d, hv);
        }
        __syncthreads();
    };

    for (int ph = 0; ph < 2; ++ph){
        const int b = g_slot[slot][ph];
        const int cell0 = b*256 + li*16;
        const int lb = li*16;

        // init state
        for (int i = tid; i < 1024; i += 512){
            ((uint32_t*)h0h)[i] = 0; ((uint32_t*)h1h)[i] = 0;
        }
        for (int i = tid; i < 2048; i += 512){ c0[i] = 0.f; c1[i] = 0.f; }
        if (tid < 16) ips[tid] = (cell0 + tid == b*256) ? 1.0f : 0.0f;
        __syncthreads();

        const int el = __ldg(exi + b);
        const bool owned = (el >> 4) == li;
        const int eloc = el & 15;
        const int nsteps = __ldg(steps + b);

        unsigned scnt = 0;
        for (int s = 0; s < nsteps; ++s){
            int par = s & 1;

            if (owned){
                int a = tid >> 7, d = tid & 127;
                if (a == 0) snC0[d] = c0[eloc*128 + d];
                else if (a == 1) snC1[d] = c1[eloc*128 + d];
                else if (a == 2) snH0[d] = hrd1(h0h, eloc, d);
                else             snH1[d] = hrd1(h1h, eloc, d);
            }
            __syncthreads();

            for (int t = 0; t < NT; ++t){
                gemm(2, g_w0t, 128, g_w1t, 256, h0h, h0h, g_xw + t*512, bls,       c0, h0h, cell0);
                gemm(4, g_w1t, 256, g_w0t, 128, h0h, h1h, nullptr,      bls + 512, c1, h1h, cell0);
            }

            if (owned){
                int a = tid >> 7, d = tid & 127;
                if (a == 0) c0[eloc*128 + d] = snC0[d];
                else if (a == 1) c1[eloc*128 + d] = snC1[d];
                else if (a == 2) hwr1(h0h, eloc, d, snH0[d]);
                else             hwr1(h1h, eloc, d, snH1[d]);
            }
            __syncthreads();

            // branch (1 cell per warp) + publish
            {
                int i = wid;
                float a0 = 0.f, a1 = 0.f;
                for (int d = lane; d < 128; d += 32){
                    float v0 = c0[i*128 + d];
                    float v1 = hrd1(h0h, i, d);
                    float v2 = c1[i*128 + d];
                    float v3 = hrd1(h1h, i, d);
                    a0 += v0*wbs[2*d]        + v1*wbs[2*(128+d)]
                        + v2*wbs[2*(256+d)]  + v3*wbs[2*(384+d)];
                    a1 += v0*wbs[2*d+1]      + v1*wbs[2*(128+d)+1]
                        + v2*wbs[2*(256+d)+1]+ v3*wbs[2*(384+d)+1];
                }
                #pragma unroll
                for (int o2 = 16; o2; o2 >>= 1){
                    a0 += __shfl_xor_sync(~0u, a0, o2);
                    a1 += __shfl_xor_sync(~0u, a1, o2);
                }
                if (lane == 0){
                    a0 += bb0; a1 += bb1;
                    float m = fmaxf(a0, a1), e0 = __expf(a0-m), e1 = __expf(a1-m);
                    float inv = 1.0f/(e0+e1), w = ips[i];
                    g_wtb[par][cell0 + i] = e0*inv*w;
                    g_wfb[par][cell0 + i] = e1*inv*w;
                }
                #pragma unroll
                for (int it = 0; it < 4; ++it){
                    int v = tid + it*512;
                    int row = v >> 7, d = v & 127;
                    size_t o = (size_t)(cell0 + row)*128 + d;
                    g_pubC[par][o]        = c0[row*128 + d];
                    g_pubC[par][o + LOFF] = c1[row*128 + d];
                    g_pubH[par][o]        = hrd1(h0h, row, d);
                    g_pubH[par][o + LOFF] = hrd1(h1h, row, d);
                }
            }
            batchsync(b, scnt);

            // aggregation (CSR)
            for (int i = tid; i < 256; i += 512){
                swt[i] = __ldcg(&g_wtb[par][b*256 + i]);
                swf[i] = __ldcg(&g_wfb[par][b*256 + i]);
            }
            __syncthreads();
            #pragma unroll
            for (int it = 0; it < 4; ++it){
                int i = it*4 + (tid >> 7);
                int d = tid & 127;
                int dstb = lb + i;
                int o0 = g_csr_off[b*NN + dstb];
                int o1 = (dstb == NN-1) ? (b*2*NN + 2*NN) : g_csr_off[b*NN + dstb + 1];
                float a0=0.f, a1=0.f, a2=0.f, a3=0.f, ipn=0.f;
                for (int qq = o0; qq < o1; ++qq){
                    int v = g_csr_ent[qq];
                    int src = v & 255;
                    float w = (v < 0) ? swf[src] : swt[src];
                    ipn += w;
                    size_t o = (size_t)(b*256 + src)*128 + d;
                    a0 += w * __ldcg(&g_pubC[par][o]);
                    a1 += w * __ldcg(&g_pubH[par][o]);
                    a2 += w * __ldcg(&g_pubC[par][o + LOFF]);
                    a3 += w * __ldcg(&g_pubH[par][o + LOFF]);
                }
                float inv = 1.0f/(ipn + 1e-7f);
                c0[i*128 + d] = a0*inv;
                c1[i*128 + d] = a2*inv;
                hwr1(h0h, i, d, a1*inv);
                hwr1(h1h, i, d, a3*inv);
                if (d == 0) ips[i] = ipn;
            }
            __syncthreads();
        }

        // ---- fused output projection for this batch ----
        if (owned){
            int a = tid >> 7, d = tid & 127;
            float v;
            if (a == 0)      v = c0[eloc*128 + d];
            else if (a == 1) v = hrd1(h0h, eloc, d);
            else if (a == 2) v = c1[eloc*128 + d];
            else             v = hrd1(h1h, eloc, d);
            g_fin[b][a*128 + d] = v;
        }
        batchsync(b, scnt);

        if (li < 8){
            float* f = (float*)(base + SNAP_OFF);      // 512 floats
            float* partial = (float*)(base + SWT_OFF); // 512 floats (swt+swf)
            for (int i = tid; i < 512; i += 512) f[i] = __ldcg(&g_fin[b][i]);
            __syncthreads();
            const int ol = tid & 127;
            const int ks = tid >> 7;
            const int o  = li * 128 + ol;
            float acc = 0.f;
            if (o < OUTV){
                const float* wp = Wo + (size_t)(ks*128) * OUTV + o;
                const float* fp = f + ks*128;
                #pragma unroll 16
                for (int k = 0; k < 128; ++k)
                    acc += fp[k] * __ldg(wp + (size_t)k * OUTV);
            }
            partial[ks*128 + ol] = acc;
            __syncthreads();
            if (ks == 0 && o < OUTV){
                float r = partial[ol] + partial[128 + ol] + partial[256 + ol] + partial[384 + ol]
                        + __ldg(bo + o);
                out[(size_t)b*OUTV + o] = r;
            }
            __syncthreads();
        }
    }
    asm volatile("cp.async.wait_group 0;":::"memory");
}

// ==================== xw precompute (fp16 2-pass A, 1-pass W) ====================
__global__ void __launch_bounds__(256,1) xwgemm()
{
    extern __shared__ char smem[];
    const uint32_t BUF0 = (smem_u32(smem) + 127u) & ~127u;
    float* Z = (float*)(smem + (BUF0 - smem_u32(smem)));
    const int tid = threadIdx.x, lane = tid & 31, wid = tid >> 5;
    const int mw = wid & 3, nw = wid >> 2;
    const int rowbase = blockIdx.x * 128, nt = blockIdx.y;

    auto load_chunk = [&](int c){
        const uint32_t b = BUF0 + (uint32_t)(c & 1) * 49152u;
        const int kbase = c * 64;
        #pragma unroll
        for (int i = 0; i < 4; ++i){
            int u = tid + i * 256;
            int row = u >> 3, col16 = u & 7;
            uint32_t sw = (uint32_t)(row * 128 + ((col16 ^ (row & 7)) * 16));
            int kg = kbase + col16 * 8;
            size_t o = (size_t)(rowbase + row) * 128 + kg;
            CPA16(b + sw,         g_embf_h + o);
            CPA16(b + 16384 + sw, g_embf_l + o);
            size_t wo = (size_t)(nt * 128 + row) * 128 + kg;
            CPA16(b + 32768 + sw, g_w0xf + wo);
        }
        CP_COMMIT();
    };

    float acc[2][8][4];
    #pragma unroll
    for (int mt=0;mt<2;++mt)
        #pragma unroll
        for (int n8=0;n8<8;++n8)
            #pragma unroll
            for (int e=0;e<4;++e) acc[mt][n8][e]=0.f;

    const int arow = mw * 32 + (lane & 15);
    const uint32_t arbase = (uint32_t)(arow * 128);
    const uint32_t axr = (uint32_t)((arow & 7) << 4);
    const uint32_t acolh = (uint32_t)((lane >> 4) * 16);
    const int brow = nw * 64 + (lane & 7);
    const uint32_t bcolh = (uint32_t)(((lane >> 3) & 1) * 16);

    load_chunk(0);
    #pragma unroll
    for (int c = 0; c < 2; ++c){
        if (c + 1 < 2) load_chunk(c + 1);
        if (c + 1 < 2) asm volatile("cp.async.wait_group 1;":::"memory");
        else           asm volatile("cp.async.wait_group 0;":::"memory");
        __syncthreads();
        const uint32_t b = BUF0 + (uint32_t)(c & 1) * 49152u;
        #pragma unroll
        for (int kk = 0; kk < 4; ++kk){
            uint32_t ah[2][4], al[2][4];
            #pragma unroll
            for (int mt = 0; mt < 2; ++mt){
                uint32_t off = (uint32_t)(mt * 16 * 128) + arbase + (((uint32_t)(kk * 32) + acolh) ^ axr);
                ldmx4(ah[mt], b + off);
                ldmx4(al[mt], b + 16384 + off);
            }
            uint32_t bh[8][2];
            #pragma unroll
            for (int n8 = 0; n8 < 8; ++n8){
                int r = brow + n8 * 8;
                uint32_t off = (uint32_t)(r * 128) + (((uint32_t)(kk * 32) + bcolh) ^ ((uint32_t)((r & 7) << 4)));
                ldmx2(bh[n8], b + 32768 + off);
            }
            #pragma unroll
            for (int mt = 0; mt < 2; ++mt)
                #pragma unroll
                for (int n8 = 0; n8 < 8; ++n8) mmaf16(acc[mt][n8], ah[mt], bh[n8]);
            #pragma unroll
            for (int mt = 0; mt < 2; ++mt)
                #pragma unroll
                for (int n8 = 0; n8 < 8; ++n8) mmaf16(acc[mt][n8], al[mt], bh[n8]);
        }
        __syncthreads();
    }
    {
        const int qr = lane >> 2, qc = (lane & 3) * 2;
        #pragma unroll
        for (int mt = 0; mt < 2; ++mt){
            int r0 = mw * 32 + mt * 16 + qr;
            #pragma unroll
            for (int n8 = 0; n8 < 8; ++n8){
                int c0i = nw * 64 + n8 * 8 + qc;
                Z[r0 * ZSTR + c0i]           = acc[mt][n8][0];
                Z[r0 * ZSTR + c0i + 1]       = acc[mt][n8][1];
                Z[(r0 + 8) * ZSTR + c0i]     = acc[mt][n8][2];
                Z[(r0 + 8) * ZSTR + c0i + 1] = acc[mt][n8][3];
            }
        }
    }
    __syncthreads();
    // store to gate-interleaved xw layout: [ct][d*4 + gate]
    const int row = tid >> 1;
    const int ct = rowbase + row;
    const int cb = (tid & 1) * 64;
    #pragma unroll
    for (int q = 0; q < 64; ++q){
        int pg = nt*128 + cb + q;            // permuted col (block permutation)
        int g  = (pg >> 5) & 3;
        int d  = (pg >> 7) * 32 + (pg & 31);
        g_xw[(size_t)ct*512 + d*4 + g] = Z[row * ZSTR + cb + q];
    }
}

// ==================== fused setup kernel ====================
__global__ void setup_kernel(const int* __restrict__ data, const float* __restrict__ embed,
                             const float* __restrict__ Wi, const float* __restrict__ Wh,
                             const int* __restrict__ tb, const int* __restrict__ fb,
                             const int* __restrict__ steps, int nblk_total)
{
    const int bx = blockIdx.x, tid = threadIdx.x;
    if (bx < NB){
        // ---- CSR build ----
        int b = bx, dst = tid;
        __shared__ int stb[NN], sfb[NN], ps[NN];
        stb[dst] = tb[b*NN+dst]; sfb[dst] = fb[b*NN+dst];
        __syncthreads();
        int cnt = 0;
        for (int ss = 0; ss < NN; ++ss) cnt += (stb[ss]==dst) + (sfb[ss]==dst);
        ps[dst] = cnt; __syncthreads();
        for (int o2 = 1; o2 < NN; o2 <<= 1){
            int v = (dst >= o2) ? ps[dst-o2] : 0;
            __syncthreads();
            ps[dst] += v;
            __syncthreads();
        }
        int start = ps[dst] - cnt;
        g_csr_off[b*NN + dst] = b*2*NN + start;
        int p = b*2*NN + start;
        for (int ss = 0; ss < NN; ++ss) if (stb[ss]==dst) g_csr_ent[p++] = ss;
        for (int ss = 0; ss < NN; ++ss) if (sfb[ss]==dst) g_csr_ent[p++] = ss | (int)0x80000000;
    } else if (bx < NB + 512){
        // ---- weight conversion ----
        int i = (bx - NB)*256 + tid;
        if (i < 512*128){   // w0xf: block permutation (for xwgemm)
            int p = i>>7, k = i&127;
            int ntc = p>>7, c = p&127, g = c>>5, j = c&31;
            int orig = g*128 + ntc*32 + j;
            g_w0xf[i] = __float2half(Wi[(size_t)k*512+orig]);
        }
        if (i < 512*128){   // w0t: gate-8 permutation p = (d>>3)*32 + g*8 + (d&7)
            int p = i>>7, k = i&127;
            int blk = p>>5, g = (p>>3)&3, dl = p&7;
            int orig = g*128 + blk*8 + dl;
            g_w0t[i] = __float2half(Wh[(size_t)k*512 + orig]);
        }
        if (i < 512*256){   // w1t: gate-8 permutation
            int p = i>>8, k = i&255;
            int blk = p>>5, g = (p>>3)&3, dl = p&7;
            int orig = g*128 + blk*8 + dl;
            float v = (k<128) ? Wi[(size_t)(128+k)*512+orig] : Wh[(size_t)(128+(k-128))*512+orig];
            g_w1t[i] = __float2half(v);
        }
    } else if (bx == nblk_total - 1){
        // ---- slot scheduling: sort desc by steps, pair i with 15-i ----
        if (tid == 0){
            int ord[16];
            for (int i = 0; i < 16; ++i) ord[i] = i;
            for (int i = 1; i < 16; ++i){
                int v = ord[i], sv = steps[v], j = i;
                while (j > 0 && steps[ord[j-1]] < sv){ ord[j] = ord[j-1]; --j; }
                ord[j] = v;
            }
            for (int i = 0; i < 8; ++i){
                g_slot[i][0] = ord[i];
                g_slot[i][1] = ord[15-i];
            }
        }
    } else {
        // ---- embedding gather ----
        int i = (bx - NB - 512)*256 + tid;
        if (i < CELLS*NT*HD){
            float v = embed[(size_t)data[i>>7]*HD + (i&127)];
            f16 h = __float2half(v);
            g_embf_h[i] = h; g_embf_l[i] = __float2half(v - __half2float(h));
        }
    }
}

// ==================== host ====================
#define TSMEM_XW (98304 + 128)

extern "C" void kernel_launch(void* const* d_in, const int* in_sizes, int n_in,
                              void* d_out, int out_size)
{
    const int*   data  = (const int*)  d_in[0];
    const int*   tb    = (const int*)  d_in[1];
    const int*   fb    = (const int*)  d_in[2];
    const int*   exi   = (const int*)  d_in[3];
    const int*   steps = (const int*)  d_in[4];
    const float* embed = (const float*)d_in[5];
    const float* Wi    = (const float*)d_in[6];
    const float* Wh    = (const float*)d_in[7];
    const float* bl    = (const float*)d_in[8];
    const float* Wb    = (const float*)d_in[9];
    const float* bb    = (const float*)d_in[10];
    const float* Wo    = (const float*)d_in[11];
    const float* bo    = (const float*)d_in[12];
    float* out = (float*)d_out;

    unsigned *bctr, *bgen;
    cudaGetSymbolAddress((void**)&bctr, g_bctr);
    cudaGetSymbolAddress((void**)&bgen, g_bgen);

    cudaFuncSetAttribute(persist, cudaFuncAttributeMaxDynamicSharedMemorySize, SM_NEED);
    cudaFuncSetAttribute(xwgemm,  cudaFuncAttributeMaxDynamicSharedMemorySize, TSMEM_XW);

    cudaMemsetAsync(bctr, 0, sizeof(unsigned)*NB, 0);
    cudaMemsetAsync(bgen, 0, sizeof(unsigned)*NB, 0);

    const int gather_blocks = (CELLS*NT*HD + 255)/256;     // 8192
    const int nblk = NB + 512 + gather_blocks + 1;
    setup_kernel<<<nblk, 256>>>(data, embed, Wi, Wh, tb, fb, steps, nblk);

    xwgemm<<<dim3(CELLS*NT/128, 4), 256, TSMEM_XW>>>();

    persist<<<NCTA, 512, SM_NEED>>>(exi, steps, bl, Wb, bb, Wo, bo, out);
}